// round 11
// baseline (speedup 1.0000x reference)
#include <cuda_runtime.h>
#include <math.h>

// Problem constants (fixed by the reference setup)
#define BB   256
#define NA   24      // atoms
#define NN   23      // neighbors per atom (N-1)
#define NP   253     // pairs = NN*(NN-1)/2
#define KR   16
#define KA   32
#define NF   (KR + KA)
#define RCR  5.2f
#define RCA  3.5f
#define PI_F 3.14159265358979323846f
#define LOG2E 1.4426950408889634f

#define SCALE_UP 100.0f
#define SCALE_DN 7.888609052210118e-31f   // 2^-100

typedef unsigned long long u64;

static __device__ __forceinline__ float ex2_approx(float x) {
    float r; asm("ex2.approx.ftz.f32 %0, %1;" : "=f"(r) : "f"(x)); return r;
}
static __device__ __forceinline__ float lg2_approx(float x) {
    float r; asm("lg2.approx.ftz.f32 %0, %1;" : "=f"(r) : "f"(x)); return r;
}
// ---- packed f32x2 helpers (sm_103a; ptxas never emits these from C++) ----
static __device__ __forceinline__ u64 pack2(float lo, float hi) {
    u64 r; asm("mov.b64 %0, {%1, %2};" : "=l"(r) : "f"(lo), "f"(hi)); return r;
}
static __device__ __forceinline__ void unpack2(u64 v, float& lo, float& hi) {
    asm("mov.b64 {%0, %1}, %2;" : "=f"(lo), "=f"(hi) : "l"(v));
}
static __device__ __forceinline__ u64 mul2(u64 a, u64 b) {
    u64 d; asm("mul.rn.f32x2 %0, %1, %2;" : "=l"(d) : "l"(a), "l"(b)); return d;
}
static __device__ __forceinline__ u64 fma2v(u64 a, u64 b, u64 c) {
    u64 d; asm("fma.rn.f32x2 %0, %1, %2, %3;" : "=l"(d) : "l"(a), "l"(b), "l"(c)); return d;
}

// Compile-time pair table: pair p -> (r | c<<8), rows of triu_indices(NN, k=1)
struct PT { unsigned short v[256]; };
static constexpr PT make_pt() {
    PT t{};
    int p = 0;
    for (int r = 0; r < NN; ++r)
        for (int c = r + 1; c < NN; ++c) { t.v[p] = (unsigned short)(r | (c << 8)); ++p; }
    for (; p < 256; ++p) t.v[p] = (unsigned short)(0 | (1 << 8));  // padding pairs
    return t;
}
static __device__ const PT d_pt = make_pt();

// Per-warp shared slab. Row stride 36 floats: phase-3 STS consecutive (conflict
// free), phase-4 LDS.128 rows land on disjoint bank groups ((4*row + 4t) % 32).
struct __align__(16) WarpBuf {
    float4 nb1[24];                       // {rx, ry, rz, invd}
    float2 nb2[24];                       // {d, fA}
    float2 nb3[24];                       // {d, fR}
    u64 cp01, cp23, sp01, sp23;           // packed cos/sin of the 4 ShfA values
    u64 S01, S23, S45;                    // packed ladder pair-step factors
    __align__(16) float powb[2][4 * 36];  // (1+cos(theta-a))^32, double buffered
    __align__(16) float radf[2][8 * 36];  // envelope ladder / fallback pairdat
};

__global__ __launch_bounds__(256, 6)
void ani_feature_kernel(const float* __restrict__ coords,     // (B, NA, 3)
                        const int*   __restrict__ atom_types, // (NA,)
                        const float* __restrict__ EtaR,       // (T, KR)
                        const float* __restrict__ ShfR,
                        const float* __restrict__ Zeta,       // (T, KA)
                        const float* __restrict__ ShfZ,
                        const float* __restrict__ EtaA,
                        const float* __restrict__ ShfA,
                        float*       __restrict__ out)        // (B, NA, 48)
{
    const int warp = threadIdx.x >> 5;
    const int l    = threadIdx.x & 31;
    const int site = blockIdx.x * 8 + warp;    // one warp = one site
    const int b = site / NA;
    const int i = site - b * NA;

    __shared__ WarpBuf wb[8];
    WarpBuf& W = wb[warp];

    const int ti = atom_types[i];              // uniform broadcast LDG

    const float* Zt  = Zeta + (size_t)ti * KA;
    const float* SZt = ShfZ + (size_t)ti * KA;
    const float* EAt = EtaA + (size_t)ti * KA;
    const float* SAt = ShfA + (size_t)ti * KA;

    // ---- structure check (warp-uniform ballot) ----
    float sz0 = SZt[0];
    float dlt = (SZt[7] - sz0) * (1.0f / 7.0f);
    float eA0 = EAt[0];
    bool ok = (Zt[l] == 32.0f)
           && (EAt[l] == eA0)
           && (SAt[l] == SAt[l & ~7])
           && (SZt[l] == SZt[l & 7])
           && (fabsf(SZt[l & 7] - (sz0 + (float)(l & 7) * dlt)) < 1e-4f);
    const bool fast = (__ballot_sync(0xffffffffu, ok) == 0xffffffffu);

    // ---- derived constants -> per-warp smem (keeps register count low) ----
    const float eAc = eA0 * LOG2E;
    const float c1c = 2.0f * eAc * dlt;
    float rr0;
    if (fast) {
        float sb, cb;
        sincosf(SAt[(l & 3) * 8], &sb, &cb);            // lanes 0..3 hold the 4 angles
        float ed2 = eAc * dlt * dlt;
        float rr  = ex2_approx(-ed2 * (float)(2 * (l & 7) + 1));   // lanes 0..6 valid
        float Sv  = rr * __shfl_down_sync(0xffffffffu, rr, 1);
        rr0 = __shfl_sync(0xffffffffu, rr, 0);
        float c1v = __shfl_sync(0xffffffffu, cb, 2 * (l & 3));
        float c2v = __shfl_sync(0xffffffffu, cb, 2 * (l & 3) + 1);
        float s1v = __shfl_sync(0xffffffffu, sb, 2 * (l & 3));
        float s2v = __shfl_sync(0xffffffffu, sb, 2 * (l & 3) + 1);
        float S1v = __shfl_sync(0xffffffffu, Sv, 2 * (l & 3));
        float S2v = __shfl_sync(0xffffffffu, Sv, 2 * (l & 3) + 1);
        if (l == 0) { W.cp01 = pack2(c1v, c2v); W.sp01 = pack2(s1v, s2v); W.S01 = pack2(S1v, S2v); }
        if (l == 1) { W.cp23 = pack2(c1v, c2v); W.sp23 = pack2(s1v, s2v); W.S23 = pack2(S1v, S2v); }
        if (l == 2) { W.S45 = pack2(S1v, S2v); }
    } else {
        rr0 = 0.0f;
    }

    // ---- Phase 1: neighbor geometry (lanes 0..22) ----
    if (l < NN) {
        const int j = (l < i) ? l : l + 1;
        const float* ci = coords + (size_t)(b * NA + i) * 3;
        const float* cj = coords + (size_t)(b * NA + j) * 3;
        float rx = ci[0] - cj[0];
        float ry = ci[1] - cj[1];
        float rz = ci[2] - cj[2];
        float d  = sqrtf(rx * rx + ry * ry + rz * rz);
        float fR = 0.5f * (cosf(d * (PI_F / RCR)) + 1.0f);
        float fA = 0.5f * (cosf(d * (PI_F / RCA)) + 1.0f);
        W.nb1[l] = make_float4(rx, ry, rz, __frcp_rn(d));
        W.nb2[l] = make_float2(d, fA);
        W.nb3[l] = make_float2(d, fR);
    }
    __syncwarp();

    // ---- Phase 2: radial G2 (lane = feature l%16, half = l/16; shfl combine) ----
    float g2acc = 0.0f;
    {
        const int k = l & 15;
        const float er = EtaR[ti * KR + k], sr = ShfR[ti * KR + k];
        for (int j = (l >> 4); j < NN; j += 2) {
            float2 df = W.nb3[j];
            float t = df.x - sr;
            g2acc += __expf(-er * t * t) * df.y;
        }
        g2acc += __shfl_xor_sync(0xffffffffu, g2acc, 16);
    }

    // ---- Phase 3+4: chunked pair loop, double buffered, 1 syncwarp/chunk ----
    u64 accA0 = 0ULL, accA1 = 0ULL, accB0 = 0ULL, accB1 = 0ULL;
    float accF = 0.0f;                // fallback accumulator
    #pragma unroll 2
    for (int ch = 0; ch < 8; ++ch) {
        const int par = ch & 1;
        const int p = ch * 32 + l;
        const unsigned short rc = d_pt.v[p];
        const int r = rc & 0xFF, c = rc >> 8;
        float4 A1 = W.nb1[r];
        float4 B1 = W.nb1[c];
        float2 A2 = W.nb2[r];
        float2 B2 = W.nb2[c];
        float dot = A1.x * B1.x + A1.y * B1.y + A1.z * B1.z;
        float cs = dot * A1.w * B1.w;
        cs = fminf(fmaxf(cs, -1.0f + 1e-7f), 1.0f - 1e-7f);
        float sn = sqrtf(fmaxf(0.0f, 1.0f - cs * cs));
        float dz = 0.5f * (A2.x + B2.x);
        float fw = (p < NP) ? A2.y * B2.y : 0.0f;

        if (fast) {
            // 4 angular powers (1+cos(theta-a))^32 via packed repeated squaring
            const u64 ONE2 = 0x3f8000003f800000ULL;
            u64 cs2 = pack2(cs, cs), sn2 = pack2(sn, sn);
            u64 x01 = fma2v(cs2, W.cp01, fma2v(sn2, W.sp01, ONE2));
            u64 x23 = fma2v(cs2, W.cp23, fma2v(sn2, W.sp23, ONE2));
            x01 = mul2(x01, x01); x01 = mul2(x01, x01); x01 = mul2(x01, x01);
            x01 = mul2(x01, x01); x01 = mul2(x01, x01);
            x23 = mul2(x23, x23); x23 = mul2(x23, x23); x23 = mul2(x23, x23);
            x23 = mul2(x23, x23); x23 = mul2(x23, x23);
            float p0, p1, p2, p3;
            unpack2(x01, p0, p1); unpack2(x23, p2, p3);
            float* pw = W.powb[par];
            pw[0 * 36 + l] = p0;  pw[1 * 36 + l] = p1;
            pw[2 * 36 + l] = p2;  pw[3 * 36 + l] = p3;

            // 8 radial envelopes: 2^100-scaled geometric ladder (2 MUFU)
            float u = dz - sz0;
            float A = ex2_approx(fmaf(-eAc * u, u, SCALE_UP));
            float R = ex2_approx(c1c * u);
            float unsc = fw * SCALE_DN;
            float v0 = A * unsc;
            float v1 = v0 * R * rr0;
            u64 R22 = pack2(R * R, R * R);
            u64 v01 = pack2(v0, v1);
            u64 v23 = mul2(v01, mul2(R22, W.S01));
            u64 v45 = mul2(v23, mul2(R22, W.S23));
            u64 v67 = mul2(v45, mul2(R22, W.S45));
            float f2, f3, f4, f5, f6, f7;
            unpack2(v23, f2, f3); unpack2(v45, f4, f5); unpack2(v67, f6, f7);
            float* rf = W.radf[par];
            rf[0 * 36 + l] = v0;  rf[1 * 36 + l] = v1;
            rf[2 * 36 + l] = f2;  rf[3 * 36 + l] = f3;
            rf[4 * 36 + l] = f4;  rf[5 * 36 + l] = f5;
            rf[6 * 36 + l] = f6;  rf[7 * 36 + l] = f7;
        } else {
            reinterpret_cast<float4*>(W.radf[par])[l] = make_float4(cs, sn, dz, fw);
        }
        __syncwarp();

        if (fast) {
            // lane l = feature (a = l/8, z = l%8) over this chunk's 32 pairs
            const ulonglong2* pp =
                reinterpret_cast<const ulonglong2*>(W.powb[par] + (l >> 3) * 36);
            const ulonglong2* rp =
                reinterpret_cast<const ulonglong2*>(W.radf[par] + (l & 7) * 36);
            #pragma unroll
            for (int t = 0; t < 8; t += 2) {
                ulonglong2 P0 = pp[t];
                ulonglong2 Q0 = rp[t];
                ulonglong2 P1 = pp[t + 1];
                ulonglong2 Q1 = rp[t + 1];
                accA0 = fma2v(P0.x, Q0.x, accA0);
                accB0 = fma2v(P0.y, Q0.y, accB0);
                accA1 = fma2v(P1.x, Q1.x, accA1);
                accB1 = fma2v(P1.y, Q1.y, accB1);
            }
        } else {
            // cold path: params reloaded per chunk to avoid live registers
            const float zk  = Zt[l];
            const float sZk = SZt[l];
            const float e2k = -EAt[l] * LOG2E;
            float sak, cak;
            sincosf(SAt[l], &sak, &cak);
            const float4* pairdat = reinterpret_cast<const float4*>(W.radf[par]);
            #pragma unroll 4
            for (int q = 0; q < 32; ++q) {
                float4 pd = pairdat[q];
                float cosang = fmaf(pd.x, cak, pd.y * sak);
                float lg = lg2_approx(1.0f + cosang);
                float dd = pd.z - sZk;
                float e  = fmaf(zk, lg, (e2k * dd) * dd);
                accF = fmaf(ex2_approx(e), pd.w, accF);
            }
        }
        // no trailing syncwarp: next chunk writes the other buffer; this
        // chunk's reads are ordered before the next syncwarp in program order.
    }

    // ---- Phase 5: output (fully warp-local) ----
    float* osite = out + (size_t)site * NF;
    if (fast) {
        u64 accT = fma2v(accA0, 0x3f8000003f800000ULL,
                         fma2v(accA1, 0x3f8000003f800000ULL,
                               fma2v(accB0, 0x3f8000003f800000ULL, accB1)));
        float a0, a1;
        unpack2(accT, a0, a1);
        osite[KR + l] = 0x1p-31f * (a0 + a1);   // 2^(1-zeta), zeta=32
    } else {
        osite[KR + l] = exp2f(1.0f - Zt[l]) * accF;
    }
    if (l < KR) osite[l] = g2acc;
}

extern "C" void kernel_launch(void* const* d_in, const int* in_sizes, int n_in,
                              void* d_out, int out_size) {
    const float* coords     = (const float*)d_in[0];
    const int*   atom_types = (const int*)  d_in[1];
    const float* EtaR       = (const float*)d_in[2];
    const float* ShfR       = (const float*)d_in[3];
    const float* Zeta       = (const float*)d_in[4];
    const float* ShfZ       = (const float*)d_in[5];
    const float* EtaA       = (const float*)d_in[6];
    const float* ShfA       = (const float*)d_in[7];
    float* out = (float*)d_out;

    ani_feature_kernel<<<(BB * NA) / 8, 256>>>(coords, atom_types, EtaR, ShfR,
                                               Zeta, ShfZ, EtaA, ShfA, out);
}

// round 13
// speedup vs baseline: 1.0875x; 1.0875x over previous
#include <cuda_runtime.h>
#include <math.h>

// Problem constants (fixed by the reference setup)
#define BB   256
#define NA   24      // atoms
#define NN   23      // neighbors per atom (N-1)
#define NP   253     // pairs = NN*(NN-1)/2
#define KR   16
#define KA   32
#define NF   (KR + KA)
#define RCR  5.2f
#define RCA  3.5f
#define PI_F 3.14159265358979323846f
#define LOG2E 1.4426950408889634f

#define SCALE_UP 100.0f
#define SCALE_DN 7.888609052210118e-31f   // 2^-100

typedef unsigned long long u64;

static __device__ __forceinline__ float ex2_approx(float x) {
    float r; asm("ex2.approx.ftz.f32 %0, %1;" : "=f"(r) : "f"(x)); return r;
}
static __device__ __forceinline__ float lg2_approx(float x) {
    float r; asm("lg2.approx.ftz.f32 %0, %1;" : "=f"(r) : "f"(x)); return r;
}
static __device__ __forceinline__ float sqrt_approx(float x) {
    float r; asm("sqrt.approx.ftz.f32 %0, %1;" : "=f"(r) : "f"(x)); return r;
}
static __device__ __forceinline__ float rcp_approx(float x) {
    float r; asm("rcp.approx.ftz.f32 %0, %1;" : "=f"(r) : "f"(x)); return r;
}
// ---- packed f32x2 helpers (sm_103a; ptxas never emits these from C++) ----
static __device__ __forceinline__ u64 pack2(float lo, float hi) {
    u64 r; asm("mov.b64 %0, {%1, %2};" : "=l"(r) : "f"(lo), "f"(hi)); return r;
}
static __device__ __forceinline__ void unpack2(u64 v, float& lo, float& hi) {
    asm("mov.b64 {%0, %1}, %2;" : "=f"(lo), "=f"(hi) : "l"(v));
}
static __device__ __forceinline__ u64 mul2(u64 a, u64 b) {
    u64 d; asm("mul.rn.f32x2 %0, %1, %2;" : "=l"(d) : "l"(a), "l"(b)); return d;
}
static __device__ __forceinline__ u64 fma2v(u64 a, u64 b, u64 c) {
    u64 d; asm("fma.rn.f32x2 %0, %1, %2, %3;" : "=l"(d) : "l"(a), "l"(b), "l"(c)); return d;
}

// Compile-time pair table: pair p -> (r | c<<8), rows of triu_indices(NN, k=1)
struct PT { unsigned short v[256]; };
static constexpr PT make_pt() {
    PT t{};
    int p = 0;
    for (int r = 0; r < NN; ++r)
        for (int c = r + 1; c < NN; ++c) { t.v[p] = (unsigned short)(r | (c << 8)); ++p; }
    for (; p < 256; ++p) t.v[p] = (unsigned short)(0 | (1 << 8));  // padding pairs
    return t;
}
static __device__ const PT d_pt = make_pt();

// Per-warp shared slab. Row stride 36 floats: phase-3 STS consecutive (conflict
// free), phase-4 LDS.128 rows land on disjoint bank groups ((4*row + 4t) % 32).
struct __align__(16) WarpBuf {
    float4 nb1[24];                       // {rx, ry, rz, invd}
    float2 nb2[24];                       // {d, fA}
    float2 nb3[24];                       // {d, fR}
    __align__(16) float powb[2][4 * 36];  // (1+cos(theta-a))^32, double buffered
    __align__(16) float radf[2][8 * 36];  // envelope ladder / fallback pairdat
};

__global__ __launch_bounds__(256)
void ani_feature_kernel(const float* __restrict__ coords,     // (B, NA, 3)
                        const int*   __restrict__ atom_types, // (NA,)
                        const float* __restrict__ EtaR,       // (T, KR)
                        const float* __restrict__ ShfR,
                        const float* __restrict__ Zeta,       // (T, KA)
                        const float* __restrict__ ShfZ,
                        const float* __restrict__ EtaA,
                        const float* __restrict__ ShfA,
                        float*       __restrict__ out)        // (B, NA, 48)
{
    const int warp = threadIdx.x >> 5;
    const int l    = threadIdx.x & 31;
    const int site = blockIdx.x * 8 + warp;    // one warp = one site
    const int b = site / NA;
    const int i = site - b * NA;

    __shared__ WarpBuf wb[8];
    WarpBuf& W = wb[warp];

    const int ti = atom_types[i];              // uniform broadcast LDG

    const float* Zt  = Zeta + (size_t)ti * KA;
    const float* SZt = ShfZ + (size_t)ti * KA;
    const float* EAt = EtaA + (size_t)ti * KA;
    const float* SAt = ShfA + (size_t)ti * KA;

    // ---- structure check (warp-uniform ballot) ----
    float sz0 = SZt[0];
    float dlt = (SZt[7] - sz0) * (1.0f / 7.0f);
    float eA0 = EAt[0];
    bool ok = (Zt[l] == 32.0f)
           && (EAt[l] == eA0)
           && (SAt[l] == SAt[l & ~7])
           && (SZt[l] == SZt[l & 7])
           && (fabsf(SZt[l & 7] - (sz0 + (float)(l & 7) * dlt)) < 1e-4f);
    const bool fast = (__ballot_sync(0xffffffffu, ok) == 0xffffffffu);

    // ---- derived constants in registers (R9 layout; approx trig) ----
    float cA0, cA1, cA2, cA3, sA0, sA1, sA2, sA3;       // cos/sin of 4 ShfA values
    float eAc, c1c, rr0, S0, S1, S2, S3, S4, S5;
    if (fast) {
        float a  = SAt[(l & 3) * 8];                    // lanes 0..3 hold the 4 angles
        float cb = __cosf(a);
        float sb = __sinf(a);
        cA0 = __shfl_sync(0xffffffffu, cb, 0); sA0 = __shfl_sync(0xffffffffu, sb, 0);
        cA1 = __shfl_sync(0xffffffffu, cb, 1); sA1 = __shfl_sync(0xffffffffu, sb, 1);
        cA2 = __shfl_sync(0xffffffffu, cb, 2); sA2 = __shfl_sync(0xffffffffu, sb, 2);
        cA3 = __shfl_sync(0xffffffffu, cb, 3); sA3 = __shfl_sync(0xffffffffu, sb, 3);
        eAc = eA0 * LOG2E;
        c1c = 2.0f * eAc * dlt;
        float ed2 = eAc * dlt * dlt;
        float rr  = ex2_approx(-ed2 * (float)(2 * (l & 7) + 1));   // lanes 0..6 valid
        float Sv  = rr * __shfl_down_sync(0xffffffffu, rr, 1);
        rr0 = __shfl_sync(0xffffffffu, rr, 0);
        S0 = __shfl_sync(0xffffffffu, Sv, 0); S1 = __shfl_sync(0xffffffffu, Sv, 1);
        S2 = __shfl_sync(0xffffffffu, Sv, 2); S3 = __shfl_sync(0xffffffffu, Sv, 3);
        S4 = __shfl_sync(0xffffffffu, Sv, 4); S5 = __shfl_sync(0xffffffffu, Sv, 5);
    } else {
        eAc = c1c = rr0 = S0 = S1 = S2 = S3 = S4 = S5 = 0.f;
        cA0 = cA1 = cA2 = cA3 = sA0 = sA1 = sA2 = sA3 = 0.f;
    }

    // ---- Phase 1: neighbor geometry (lanes 0..22; approx cos/sqrt/rcp) ----
    if (l < NN) {
        const int j = (l < i) ? l : l + 1;
        const float* ci = coords + (size_t)(b * NA + i) * 3;
        const float* cj = coords + (size_t)(b * NA + j) * 3;
        float rx = ci[0] - cj[0];
        float ry = ci[1] - cj[1];
        float rz = ci[2] - cj[2];
        float d2 = rx * rx + ry * ry + rz * rz;
        float d  = sqrt_approx(d2);
        float fR = 0.5f * (__cosf(d * (PI_F / RCR)) + 1.0f);
        float fA = 0.5f * (__cosf(d * (PI_F / RCA)) + 1.0f);
        W.nb1[l] = make_float4(rx, ry, rz, rcp_approx(d));
        W.nb2[l] = make_float2(d, fA);
        W.nb3[l] = make_float2(d, fR);
    }
    __syncwarp();

    // ---- Phase 2: radial G2 (lane = feature l%16, half = l/16; shfl combine) ----
    float g2acc = 0.0f;
    {
        const int k = l & 15;
        const float erk = -EtaR[ti * KR + k] * LOG2E;
        const float sr  = ShfR[ti * KR + k];
        for (int j = (l >> 4); j < NN; j += 2) {
            float2 df = W.nb3[j];
            float t = df.x - sr;
            g2acc += ex2_approx((erk * t) * t) * df.y;
        }
        g2acc += __shfl_xor_sync(0xffffffffu, g2acc, 16);
    }

    // ---- Phase 3+4: chunked pair loop, double buffered, 1 syncwarp/chunk ----
    u64 accA0 = 0ULL, accA1 = 0ULL, accB0 = 0ULL, accB1 = 0ULL;
    float accF = 0.0f;                // fallback accumulator
    #pragma unroll 2
    for (int ch = 0; ch < 8; ++ch) {
        const int par = ch & 1;
        const int p = ch * 32 + l;
        const unsigned short rc = d_pt.v[p];
        const int r = rc & 0xFF, c = rc >> 8;
        float4 A1 = W.nb1[r];
        float4 B1 = W.nb1[c];
        float2 A2 = W.nb2[r];
        float2 B2 = W.nb2[c];
        float dot = A1.x * B1.x + A1.y * B1.y + A1.z * B1.z;
        float cs = dot * A1.w * B1.w;
        cs = fminf(fmaxf(cs, -1.0f + 1e-7f), 1.0f - 1e-7f);
        float sn = sqrt_approx(fmaxf(0.0f, 1.0f - cs * cs));
        float dz = 0.5f * (A2.x + B2.x);
        float fw = (p < NP) ? A2.y * B2.y : 0.0f;

        if (fast) {
            // 4 angular powers (1+cos(theta-a))^32 via packed repeated squaring
            const u64 ONE2 = 0x3f8000003f800000ULL;
            u64 cs2 = pack2(cs, cs), sn2 = pack2(sn, sn);
            u64 x01 = fma2v(cs2, pack2(cA0, cA1), fma2v(sn2, pack2(sA0, sA1), ONE2));
            u64 x23 = fma2v(cs2, pack2(cA2, cA3), fma2v(sn2, pack2(sA2, sA3), ONE2));
            x01 = mul2(x01, x01); x01 = mul2(x01, x01); x01 = mul2(x01, x01);
            x01 = mul2(x01, x01); x01 = mul2(x01, x01);
            x23 = mul2(x23, x23); x23 = mul2(x23, x23); x23 = mul2(x23, x23);
            x23 = mul2(x23, x23); x23 = mul2(x23, x23);
            float p0, p1, p2, p3;
            unpack2(x01, p0, p1); unpack2(x23, p2, p3);
            float* pw = W.powb[par];
            pw[0 * 36 + l] = p0;  pw[1 * 36 + l] = p1;
            pw[2 * 36 + l] = p2;  pw[3 * 36 + l] = p3;

            // 8 radial envelopes: 2^100-scaled geometric ladder (2 MUFU)
            float u = dz - sz0;
            float A = ex2_approx(fmaf(-eAc * u, u, SCALE_UP));
            float R = ex2_approx(c1c * u);
            float unsc = fw * SCALE_DN;
            float v0 = A * unsc;
            float v1 = v0 * R * rr0;
            float R2 = R * R;
            u64 v01 = pack2(v0, v1);
            u64 v23 = mul2(v01, pack2(R2 * S0, R2 * S1));
            u64 v45 = mul2(v23, pack2(R2 * S2, R2 * S3));
            u64 v67 = mul2(v45, pack2(R2 * S4, R2 * S5));
            float f2, f3, f4, f5, f6, f7;
            unpack2(v23, f2, f3); unpack2(v45, f4, f5); unpack2(v67, f6, f7);
            float* rf = W.radf[par];
            rf[0 * 36 + l] = v0;  rf[1 * 36 + l] = v1;
            rf[2 * 36 + l] = f2;  rf[3 * 36 + l] = f3;
            rf[4 * 36 + l] = f4;  rf[5 * 36 + l] = f5;
            rf[6 * 36 + l] = f6;  rf[7 * 36 + l] = f7;
        } else {
            reinterpret_cast<float4*>(W.radf[par])[l] = make_float4(cs, sn, dz, fw);
        }
        __syncwarp();

        if (fast) {
            // lane l = feature (a = l/8, z = l%8) over this chunk's 32 pairs
            const ulonglong2* pp =
                reinterpret_cast<const ulonglong2*>(W.powb[par] + (l >> 3) * 36);
            const ulonglong2* rp =
                reinterpret_cast<const ulonglong2*>(W.radf[par] + (l & 7) * 36);
            #pragma unroll
            for (int t = 0; t < 8; t += 2) {
                ulonglong2 P0 = pp[t];
                ulonglong2 Q0 = rp[t];
                ulonglong2 P1 = pp[t + 1];
                ulonglong2 Q1 = rp[t + 1];
                accA0 = fma2v(P0.x, Q0.x, accA0);
                accB0 = fma2v(P0.y, Q0.y, accB0);
                accA1 = fma2v(P1.x, Q1.x, accA1);
                accB1 = fma2v(P1.y, Q1.y, accB1);
            }
        } else {
            // cold path: accurate libm, params reloaded per chunk
            const float zk  = Zt[l];
            const float sZk = SZt[l];
            const float e2k = -EAt[l] * LOG2E;
            float sak, cak;
            sincosf(SAt[l], &sak, &cak);
            const float4* pairdat = reinterpret_cast<const float4*>(W.radf[par]);
            #pragma unroll 4
            for (int q = 0; q < 32; ++q) {
                float4 pd = pairdat[q];
                float cosang = fmaf(pd.x, cak, pd.y * sak);
                float lg = lg2_approx(1.0f + cosang);
                float dd = pd.z - sZk;
                float e  = fmaf(zk, lg, (e2k * dd) * dd);
                accF = fmaf(ex2_approx(e), pd.w, accF);
            }
        }
        // no trailing syncwarp: next chunk writes the other buffer; this
        // chunk's reads are ordered before the next syncwarp in program order.
    }

    // ---- Phase 5: output (fully warp-local) ----
    float* osite = out + (size_t)site * NF;
    if (fast) {
        u64 accT = fma2v(accA0, 0x3f8000003f800000ULL,
                         fma2v(accA1, 0x3f8000003f800000ULL,
                               fma2v(accB0, 0x3f8000003f800000ULL, accB1)));
        float a0, a1;
        unpack2(accT, a0, a1);
        osite[KR + l] = 0x1p-31f * (a0 + a1);   // 2^(1-zeta), zeta=32
    } else {
        osite[KR + l] = exp2f(1.0f - Zt[l]) * accF;
    }
    if (l < KR) osite[l] = g2acc;
}

extern "C" void kernel_launch(void* const* d_in, const int* in_sizes, int n_in,
                              void* d_out, int out_size) {
    const float* coords     = (const float*)d_in[0];
    const int*   atom_types = (const int*)  d_in[1];
    const float* EtaR       = (const float*)d_in[2];
    const float* ShfR       = (const float*)d_in[3];
    const float* Zeta       = (const float*)d_in[4];
    const float* ShfZ       = (const float*)d_in[5];
    const float* EtaA       = (const float*)d_in[6];
    const float* ShfA       = (const float*)d_in[7];
    float* out = (float*)d_out;

    ani_feature_kernel<<<(BB * NA) / 8, 256>>>(coords, atom_types, EtaR, ShfR,
                                               Zeta, ShfZ, EtaA, ShfA, out);
}

// round 14
// speedup vs baseline: 1.1936x; 1.0976x over previous
#include <cuda_runtime.h>
#include <math.h>

// Problem constants (fixed by the reference setup)
#define BB   256
#define NA   24      // atoms
#define NN   23      // neighbors per atom (N-1)
#define NP   253     // pairs = NN*(NN-1)/2
#define KR   16
#define KA   32
#define NF   (KR + KA)
#define RCR  5.2f
#define RCA  3.5f
#define PI_F 3.14159265358979323846f
#define LOG2E 1.4426950408889634f

#define SCALE_UP 100.0f
#define SCALE_DN 7.888609052210118e-31f   // 2^-100

typedef unsigned long long u64;

static __device__ __forceinline__ float ex2_approx(float x) {
    float r; asm("ex2.approx.ftz.f32 %0, %1;" : "=f"(r) : "f"(x)); return r;
}
static __device__ __forceinline__ float lg2_approx(float x) {
    float r; asm("lg2.approx.ftz.f32 %0, %1;" : "=f"(r) : "f"(x)); return r;
}
static __device__ __forceinline__ float sqrt_approx(float x) {
    float r; asm("sqrt.approx.ftz.f32 %0, %1;" : "=f"(r) : "f"(x)); return r;
}
static __device__ __forceinline__ float rcp_approx(float x) {
    float r; asm("rcp.approx.ftz.f32 %0, %1;" : "=f"(r) : "f"(x)); return r;
}
// ---- packed f32x2 helpers (sm_103a; ptxas never emits these from C++) ----
static __device__ __forceinline__ u64 pack2(float lo, float hi) {
    u64 r; asm("mov.b64 %0, {%1, %2};" : "=l"(r) : "f"(lo), "f"(hi)); return r;
}
static __device__ __forceinline__ void unpack2(u64 v, float& lo, float& hi) {
    asm("mov.b64 {%0, %1}, %2;" : "=f"(lo), "=f"(hi) : "l"(v));
}
static __device__ __forceinline__ u64 mul2(u64 a, u64 b) {
    u64 d; asm("mul.rn.f32x2 %0, %1, %2;" : "=l"(d) : "l"(a), "l"(b)); return d;
}
static __device__ __forceinline__ u64 fma2v(u64 a, u64 b, u64 c) {
    u64 d; asm("fma.rn.f32x2 %0, %1, %2, %3;" : "=l"(d) : "l"(a), "l"(b), "l"(c)); return d;
}

// Compile-time pair table: pair p -> (r | c<<8), rows of triu_indices(NN, k=1)
struct PT { unsigned short v[256]; };
static constexpr PT make_pt() {
    PT t{};
    int p = 0;
    for (int r = 0; r < NN; ++r)
        for (int c = r + 1; c < NN; ++c) { t.v[p] = (unsigned short)(r | (c << 8)); ++p; }
    for (; p < 256; ++p) t.v[p] = (unsigned short)(0 | (1 << 8));  // padding pairs
    return t;
}
static __device__ const PT d_pt = make_pt();

// Per-warp shared slab. Row stride 36 floats: phase-3 STS consecutive (conflict
// free), phase-4 LDS.128 rows land on disjoint bank groups ((4*row + 4t) % 32).
struct __align__(16) WarpBuf {
    float4 nb1[24];                       // {rx, ry, rz, invd}
    float2 nb2[24];                       // {d, fA}
    float2 nb3[24];                       // {d, fR}
    __align__(16) float powb[2][4 * 36];  // (1+cos(theta-a))^32, double buffered
    __align__(16) float radf[2][8 * 36];  // envelope ladder
};

struct G4 { float cs, sn, dz, fw; };

static __device__ __forceinline__ G4 pair_geom(const WarpBuf& W, int p) {
    const unsigned short rc = d_pt.v[p];
    const int r = rc & 0xFF, c = rc >> 8;
    float4 A1 = W.nb1[r];
    float4 B1 = W.nb1[c];
    float2 A2 = W.nb2[r];
    float2 B2 = W.nb2[c];
    float dot = A1.x * B1.x + A1.y * B1.y + A1.z * B1.z;
    float cs = dot * A1.w * B1.w;
    cs = fminf(fmaxf(cs, -1.0f + 1e-7f), 1.0f - 1e-7f);
    G4 g;
    g.cs = cs;
    g.sn = sqrt_approx(fmaxf(0.0f, 1.0f - cs * cs));
    g.dz = 0.5f * (A2.x + B2.x);
    g.fw = (p < NP) ? A2.y * B2.y : 0.0f;
    return g;
}

static __device__ __forceinline__ void emit_pair(
    WarpBuf& W, int par, int l, const G4& g,
    u64 cp01, u64 cp23, u64 sp01, u64 sp23,
    u64 S01, u64 S23, u64 S45,
    float sz0, float eAc, float c1c, float rr0)
{
    // 4 angular powers (1+cos(theta-a))^32 via packed repeated squaring
    const u64 ONE2 = 0x3f8000003f800000ULL;
    u64 cs2 = pack2(g.cs, g.cs), sn2 = pack2(g.sn, g.sn);
    u64 x01 = fma2v(cs2, cp01, fma2v(sn2, sp01, ONE2));
    u64 x23 = fma2v(cs2, cp23, fma2v(sn2, sp23, ONE2));
    x01 = mul2(x01, x01); x01 = mul2(x01, x01); x01 = mul2(x01, x01);
    x01 = mul2(x01, x01); x01 = mul2(x01, x01);
    x23 = mul2(x23, x23); x23 = mul2(x23, x23); x23 = mul2(x23, x23);
    x23 = mul2(x23, x23); x23 = mul2(x23, x23);
    float p0, p1, p2, p3;
    unpack2(x01, p0, p1); unpack2(x23, p2, p3);
    float* pw = W.powb[par];
    pw[0 * 36 + l] = p0;  pw[1 * 36 + l] = p1;
    pw[2 * 36 + l] = p2;  pw[3 * 36 + l] = p3;

    // 8 radial envelopes: 2^100-scaled geometric ladder (2 MUFU)
    float u = g.dz - sz0;
    float A = ex2_approx(fmaf(-eAc * u, u, SCALE_UP));
    float R = ex2_approx(c1c * u);
    float unsc = g.fw * SCALE_DN;
    float v0 = A * unsc;
    float v1 = v0 * R * rr0;
    u64 R22 = pack2(R * R, R * R);
    u64 v01 = pack2(v0, v1);
    u64 v23 = mul2(v01, mul2(R22, S01));
    u64 v45 = mul2(v23, mul2(R22, S23));
    u64 v67 = mul2(v45, mul2(R22, S45));
    float f2, f3, f4, f5, f6, f7;
    unpack2(v23, f2, f3); unpack2(v45, f4, f5); unpack2(v67, f6, f7);
    float* rf = W.radf[par];
    rf[0 * 36 + l] = v0;  rf[1 * 36 + l] = v1;
    rf[2 * 36 + l] = f2;  rf[3 * 36 + l] = f3;
    rf[4 * 36 + l] = f4;  rf[5 * 36 + l] = f5;
    rf[6 * 36 + l] = f6;  rf[7 * 36 + l] = f7;
}

// Cold generic path (accurate libm) — isolated so its registers/code do not
// pollute the hot path.
static __device__ __noinline__ void generic_g3(
    const WarpBuf& W, const float* Zt, const float* SZt,
    const float* EAt, const float* SAt,
    float g2acc, float* osite, int l)
{
    const float zk  = Zt[l];
    const float sZk = SZt[l];
    const float e2k = -EAt[l] * LOG2E;
    float sak, cak;
    sincosf(SAt[l], &sak, &cak);
    float acc = 0.0f;
    for (int p = 0; p < NP; ++p) {
        const unsigned short rc = d_pt.v[p];
        const int r = rc & 0xFF, c = rc >> 8;
        float4 A1 = W.nb1[r];
        float4 B1 = W.nb1[c];
        float2 A2 = W.nb2[r];
        float2 B2 = W.nb2[c];
        float dot = A1.x * B1.x + A1.y * B1.y + A1.z * B1.z;
        float cs = dot * A1.w * B1.w;
        cs = fminf(fmaxf(cs, -1.0f + 1e-7f), 1.0f - 1e-7f);
        float sn = sqrtf(fmaxf(0.0f, 1.0f - cs * cs));
        float dz = 0.5f * (A2.x + B2.x);
        float fw = A2.y * B2.y;
        float cosang = fmaf(cs, cak, sn * sak);
        float lg = lg2_approx(1.0f + cosang);
        float dd = dz - sZk;
        float e  = fmaf(zk, lg, (e2k * dd) * dd);
        acc = fmaf(ex2_approx(e), fw, acc);
    }
    osite[KR + l] = exp2f(1.0f - zk) * acc;
    if (l < KR) osite[l] = g2acc;
}

__global__ __launch_bounds__(256)
void ani_feature_kernel(const float* __restrict__ coords,     // (B, NA, 3)
                        const int*   __restrict__ atom_types, // (NA,)
                        const float* __restrict__ EtaR,       // (T, KR)
                        const float* __restrict__ ShfR,
                        const float* __restrict__ Zeta,       // (T, KA)
                        const float* __restrict__ ShfZ,
                        const float* __restrict__ EtaA,
                        const float* __restrict__ ShfA,
                        float*       __restrict__ out)        // (B, NA, 48)
{
    const int warp = threadIdx.x >> 5;
    const int l    = threadIdx.x & 31;
    const int site = blockIdx.x * 8 + warp;    // one warp = one site
    const int b = site / NA;
    const int i = site - b * NA;

    __shared__ WarpBuf wb[8];
    WarpBuf& W = wb[warp];

    const int ti = atom_types[i];              // uniform broadcast LDG

    const float* Zt  = Zeta + (size_t)ti * KA;
    const float* SZt = ShfZ + (size_t)ti * KA;
    const float* EAt = EtaA + (size_t)ti * KA;
    const float* SAt = ShfA + (size_t)ti * KA;

    // ---- structure check (warp-uniform ballot) ----
    float sz0 = SZt[0];
    float dlt = (SZt[7] - sz0) * (1.0f / 7.0f);
    float eA0 = EAt[0];
    bool ok = (Zt[l] == 32.0f)
           && (EAt[l] == eA0)
           && (SAt[l] == SAt[l & ~7])
           && (SZt[l] == SZt[l & 7])
           && (fabsf(SZt[l & 7] - (sz0 + (float)(l & 7) * dlt)) < 1e-4f);
    const bool fast = (__ballot_sync(0xffffffffu, ok) == 0xffffffffu);

    // ---- Phase 1: neighbor geometry (lanes 0..22; approx cos/sqrt/rcp) ----
    if (l < NN) {
        const int j = (l < i) ? l : l + 1;
        const float* ci = coords + (size_t)(b * NA + i) * 3;
        const float* cj = coords + (size_t)(b * NA + j) * 3;
        float rx = ci[0] - cj[0];
        float ry = ci[1] - cj[1];
        float rz = ci[2] - cj[2];
        float d  = sqrt_approx(rx * rx + ry * ry + rz * rz);
        float fR = 0.5f * (__cosf(d * (PI_F / RCR)) + 1.0f);
        float fA = 0.5f * (__cosf(d * (PI_F / RCA)) + 1.0f);
        W.nb1[l] = make_float4(rx, ry, rz, rcp_approx(d));
        W.nb2[l] = make_float2(d, fA);
        W.nb3[l] = make_float2(d, fR);
    }
    __syncwarp();

    // ---- Phase 2: radial G2 (lane = feature l%16, half = l/16; shfl combine) ----
    float g2acc = 0.0f;
    {
        const int k = l & 15;
        const float erk = -EtaR[ti * KR + k] * LOG2E;
        const float sr  = ShfR[ti * KR + k];
        for (int j = (l >> 4); j < NN; j += 2) {
            float2 df = W.nb3[j];
            float t = df.x - sr;
            g2acc += ex2_approx((erk * t) * t) * df.y;
        }
        g2acc += __shfl_xor_sync(0xffffffffu, g2acc, 16);
    }

    float* osite = out + (size_t)site * NF;

    if (!fast) {                               // cold, isolated path
        generic_g3(W, Zt, SZt, EAt, SAt, g2acc, osite, l);
        return;
    }

    // ---- derived constants, pre-packed into registers ----
    const float eAc = eA0 * LOG2E;
    const float c1c = 2.0f * eAc * dlt;
    u64 cp01, cp23, sp01, sp23, S01, S23, S45;
    float rr0;
    {
        float a  = SAt[(l & 3) * 8];                   // lanes 0..3: the 4 angles
        float cb = __cosf(a);
        float sb = __sinf(a);
        cp01 = pack2(__shfl_sync(0xffffffffu, cb, 0), __shfl_sync(0xffffffffu, cb, 1));
        cp23 = pack2(__shfl_sync(0xffffffffu, cb, 2), __shfl_sync(0xffffffffu, cb, 3));
        sp01 = pack2(__shfl_sync(0xffffffffu, sb, 0), __shfl_sync(0xffffffffu, sb, 1));
        sp23 = pack2(__shfl_sync(0xffffffffu, sb, 2), __shfl_sync(0xffffffffu, sb, 3));
        float ed2 = eAc * dlt * dlt;
        float rr  = ex2_approx(-ed2 * (float)(2 * (l & 7) + 1));   // lanes 0..6 valid
        float Sv  = rr * __shfl_down_sync(0xffffffffu, rr, 1);
        rr0 = __shfl_sync(0xffffffffu, rr, 0);
        S01 = pack2(__shfl_sync(0xffffffffu, Sv, 0), __shfl_sync(0xffffffffu, Sv, 1));
        S23 = pack2(__shfl_sync(0xffffffffu, Sv, 2), __shfl_sync(0xffffffffu, Sv, 3));
        S45 = pack2(__shfl_sync(0xffffffffu, Sv, 4), __shfl_sync(0xffffffffu, Sv, 5));
    }

    // ---- Software-pipelined chunk loop: geom(ch+1) || acc(ch), 1 sync/chunk ----
    u64 accA0 = 0ULL, accA1 = 0ULL, accB0 = 0ULL, accB1 = 0ULL;

    {
        G4 g0 = pair_geom(W, l);               // chunk 0
        emit_pair(W, 0, l, g0, cp01, cp23, sp01, sp23, S01, S23, S45,
                  sz0, eAc, c1c, rr0);
    }
    __syncwarp();

    int par = 0;
    const int rowP = (l >> 3) * 36;            // pow row offset for this lane
    const int rowR = (l & 7) * 36;             // radf row offset for this lane
    for (int ch = 0; ch < 7; ++ch) {
        // prefetch next chunk's geometry (overlaps with row reads below)
        G4 gn = pair_geom(W, (ch + 1) * 32 + l);

        // accumulate current chunk
        const ulonglong2* pp = reinterpret_cast<const ulonglong2*>(W.powb[par] + rowP);
        const ulonglong2* rp = reinterpret_cast<const ulonglong2*>(W.radf[par] + rowR);
        #pragma unroll
        for (int t = 0; t < 8; t += 2) {
            ulonglong2 P0 = pp[t];
            ulonglong2 Q0 = rp[t];
            ulonglong2 P1 = pp[t + 1];
            ulonglong2 Q1 = rp[t + 1];
            accA0 = fma2v(P0.x, Q0.x, accA0);
            accB0 = fma2v(P0.y, Q0.y, accB0);
            accA1 = fma2v(P1.x, Q1.x, accA1);
            accB1 = fma2v(P1.y, Q1.y, accB1);
        }

        // emit next chunk into the other buffer (last read before prev sync)
        emit_pair(W, par ^ 1, l, gn, cp01, cp23, sp01, sp23, S01, S23, S45,
                  sz0, eAc, c1c, rr0);
        __syncwarp();
        par ^= 1;
    }
    {   // final chunk accumulate
        const ulonglong2* pp = reinterpret_cast<const ulonglong2*>(W.powb[par] + rowP);
        const ulonglong2* rp = reinterpret_cast<const ulonglong2*>(W.radf[par] + rowR);
        #pragma unroll
        for (int t = 0; t < 8; t += 2) {
            ulonglong2 P0 = pp[t];
            ulonglong2 Q0 = rp[t];
            ulonglong2 P1 = pp[t + 1];
            ulonglong2 Q1 = rp[t + 1];
            accA0 = fma2v(P0.x, Q0.x, accA0);
            accB0 = fma2v(P0.y, Q0.y, accB0);
            accA1 = fma2v(P1.x, Q1.x, accA1);
            accB1 = fma2v(P1.y, Q1.y, accB1);
        }
    }

    // ---- output (fully warp-local) ----
    u64 accT = fma2v(accA0, 0x3f8000003f800000ULL,
                     fma2v(accA1, 0x3f8000003f800000ULL,
                           fma2v(accB0, 0x3f8000003f800000ULL, accB1)));
    float a0, a1;
    unpack2(accT, a0, a1);
    osite[KR + l] = 0x1p-31f * (a0 + a1);      // 2^(1-zeta), zeta=32
    if (l < KR) osite[l] = g2acc;
}

extern "C" void kernel_launch(void* const* d_in, const int* in_sizes, int n_in,
                              void* d_out, int out_size) {
    const float* coords     = (const float*)d_in[0];
    const int*   atom_types = (const int*)  d_in[1];
    const float* EtaR       = (const float*)d_in[2];
    const float* ShfR       = (const float*)d_in[3];
    const float* Zeta       = (const float*)d_in[4];
    const float* ShfZ       = (const float*)d_in[5];
    const float* EtaA       = (const float*)d_in[6];
    const float* ShfA       = (const float*)d_in[7];
    float* out = (float*)d_out;

    ani_feature_kernel<<<(BB * NA) / 8, 256>>>(coords, atom_types, EtaR, ShfR,
                                               Zeta, ShfZ, EtaA, ShfA, out);
}